// round 17
// baseline (speedup 1.0000x reference)
#include <cuda_runtime.h>
#include <cuda_bf16.h>
#include <cstdint>
#include <math.h>

#define B_  32
#define N_  64
#define D_  30
#define ND_ 64
#define H3_ 32
#define L_  8

typedef unsigned long long u64;

// packed f32x2 helpers (Blackwell)
#define FMA2(d,a,b,c) asm("fma.rn.f32x2 %0,%1,%2,%3;" : "=l"(d) : "l"(a), "l"(b), "l"(c))
#define ADD2(d,a,b)   asm("add.rn.f32x2 %0,%1,%2;"    : "=l"(d) : "l"(a), "l"(b))
__device__ __forceinline__ u64 pk2(float lo, float hi){
    u64 r; asm("mov.b64 %0,{%1,%2};" : "=l"(r) : "f"(lo), "f"(hi)); return r;
}
__device__ __forceinline__ void upk2(u64 v, float& lo, float& hi){
    asm("mov.b64 {%0,%1},%2;" : "=f"(lo), "=f"(hi) : "l"(v));
}

// ---------------- device scratch ----------------
__device__ float g_xenc[B_*N_*H3_];
__device__ float g_x2[B_*N_];
__device__ float g_denc[D_*ND_*H3_];
__device__ float g_dsamp[D_*ND_*H3_];
__device__ float g_y2[D_*ND_];
__device__ float g_klpart[D_];
__device__ float4 g_vwd[D_*N_*ND_];
__device__ float4 g_part[L_*B_*D_];

__constant__ float c_lamda[8] = {0.01f,0.1f,0.5f,1.0f,3.0f,5.0f,10.0f,20.0f};

// group barrier: 256 threads of lambda-group g (ids 1,2)
#define GBAR(g) asm volatile("bar.sync %0, %1;" :: "r"((g)+1), "r"(256) : "memory")

// ---------------- JAX threefry2x32 (partitionable) ------------------
__device__ __forceinline__ uint32_t rotl32(uint32_t x, int r){
    return (x << r) | (x >> (32 - r));
}
__device__ float jax_uniform_1920(int i){
    uint32_t x0 = 0u;
    uint32_t x1 = (uint32_t)i;
    const uint32_t k0 = 0u, k1 = 42u;
    const uint32_t k2 = 0u ^ 42u ^ 0x1BD11BDAu;
    x0 += k0; x1 += k1;
    #define FOUR_ROUNDS(a,b,c,d) \
        x0 += x1; x1 = rotl32(x1,a); x1 ^= x0; \
        x0 += x1; x1 = rotl32(x1,b); x1 ^= x0; \
        x0 += x1; x1 = rotl32(x1,c); x1 ^= x0; \
        x0 += x1; x1 = rotl32(x1,d); x1 ^= x0;
    FOUR_ROUNDS(13,15,26,6);  x0 += k1; x1 += k2 + 1u;
    FOUR_ROUNDS(17,29,16,24); x0 += k2; x1 += k0 + 2u;
    FOUR_ROUNDS(13,15,26,6);  x0 += k0; x1 += k1 + 3u;
    FOUR_ROUNDS(17,29,16,24); x0 += k1; x1 += k2 + 4u;
    FOUR_ROUNDS(13,15,26,6);  x0 += k2; x1 += k0 + 5u;
    #undef FOUR_ROUNDS
    uint32_t bits = x0 ^ x1;
    uint32_t fb = (bits >> 9) | 0x3f800000u;
    return __uint_as_float(fb) - 1.0f;
}

// ---------------- GCN (both branches, 512 threads) ------------------------
__global__ void gcn_kernel(
    const float* __restrict__ xg0, const float* __restrict__ adjg0,
    const float* __restrict__ eW1, const float* __restrict__ eb1,
    const float* __restrict__ eW2, const float* __restrict__ eb2,
    const float* __restrict__ eW3, const float* __restrict__ eb3,
    const float* __restrict__ xg1, const float* __restrict__ adjg1,
    const float* __restrict__ dW1, const float* __restrict__ db1,
    const float* __restrict__ dW2, const float* __restrict__ db2,
    const float* __restrict__ dW3, const float* __restrict__ db3)
{
    extern __shared__ float sm[];
    float* adj_s = sm;             // 4096
    float* x_s   = sm + 4096;      // 4096
    float* t     = sm + 8192;      // 8192
    float* h     = sm + 16384;     // 8192
    int branch = (blockIdx.x >= 32) ? 1 : 0;
    int g = branch ? (blockIdx.x - 32) : blockIdx.x;
    const float* x   = (branch ? xg1   : xg0)   + g*64*64;
    const float* adj = (branch ? adjg1 : adjg0) + g*64*64;
    const float* W1 = branch ? dW1 : eW1; const float* b1 = branch ? db1 : eb1;
    const float* W2 = branch ? dW2 : eW2; const float* b2 = branch ? db2 : eb2;
    const float* W3 = branch ? dW3 : eW3; const float* b3 = branch ? db3 : eb3;
    int tid = threadIdx.x;

    for (int i = tid; i < 4096; i += 512){ adj_s[i] = adj[i]; x_s[i] = x[i]; }
    __syncthreads();

    for (int idx = tid; idx < 16*128; idx += 512){
        int rg = idx >> 7, j = idx & 127;
        const float* xr = x_s + rg*4*64;
        float a0=0.f,a1=0.f,a2=0.f,a3=0.f;
        #pragma unroll 8
        for (int k = 0; k < 64; k++){
            float w = W1[k*128+j];
            a0 += xr[k]*w; a1 += xr[64+k]*w; a2 += xr[128+k]*w; a3 += xr[192+k]*w;
        }
        t[(rg*4+0)*128+j]=a0; t[(rg*4+1)*128+j]=a1; t[(rg*4+2)*128+j]=a2; t[(rg*4+3)*128+j]=a3;
    }
    __syncthreads();
    for (int idx = tid; idx < 16*128; idx += 512){
        int rg = idx >> 7, j = idx & 127;
        const float* ar = adj_s + rg*4*64;
        float bb = b1[j];
        float a0=bb,a1=bb,a2=bb,a3=bb;
        #pragma unroll 8
        for (int k = 0; k < 64; k++){
            float w = t[k*128+j];
            a0 += ar[k]*w; a1 += ar[64+k]*w; a2 += ar[128+k]*w; a3 += ar[192+k]*w;
        }
        h[(rg*4+0)*128+j]=fmaxf(a0,0.f); h[(rg*4+1)*128+j]=fmaxf(a1,0.f);
        h[(rg*4+2)*128+j]=fmaxf(a2,0.f); h[(rg*4+3)*128+j]=fmaxf(a3,0.f);
    }
    __syncthreads();
    for (int idx = tid; idx < 16*64; idx += 512){
        int rg = idx >> 6, j = idx & 63;
        const float* hr = h + rg*4*128;
        float a0=0.f,a1=0.f,a2=0.f,a3=0.f;
        #pragma unroll 8
        for (int k = 0; k < 128; k++){
            float w = W2[k*64+j];
            a0 += hr[k]*w; a1 += hr[128+k]*w; a2 += hr[256+k]*w; a3 += hr[384+k]*w;
        }
        t[(rg*4+0)*64+j]=a0; t[(rg*4+1)*64+j]=a1; t[(rg*4+2)*64+j]=a2; t[(rg*4+3)*64+j]=a3;
    }
    __syncthreads();
    for (int idx = tid; idx < 16*64; idx += 512){
        int rg = idx >> 6, j = idx & 63;
        const float* ar = adj_s + rg*4*64;
        float bb = b2[j];
        float a0=bb,a1=bb,a2=bb,a3=bb;
        #pragma unroll 8
        for (int k = 0; k < 64; k++){
            float w = t[k*64+j];
            a0 += ar[k]*w; a1 += ar[64+k]*w; a2 += ar[128+k]*w; a3 += ar[192+k]*w;
        }
        h[(rg*4+0)*64+j]=fmaxf(a0,0.f); h[(rg*4+1)*64+j]=fmaxf(a1,0.f);
        h[(rg*4+2)*64+j]=fmaxf(a2,0.f); h[(rg*4+3)*64+j]=fmaxf(a3,0.f);
    }
    __syncthreads();
    for (int idx = tid; idx < 16*32; idx += 512){
        int rg = idx >> 5, j = idx & 31;
        const float* hr = h + rg*4*64;
        float a0=0.f,a1=0.f,a2=0.f,a3=0.f;
        #pragma unroll 8
        for (int k = 0; k < 64; k++){
            float w = W3[k*32+j];
            a0 += hr[k]*w; a1 += hr[64+k]*w; a2 += hr[128+k]*w; a3 += hr[192+k]*w;
        }
        t[(rg*4+0)*32+j]=a0; t[(rg*4+1)*32+j]=a1; t[(rg*4+2)*32+j]=a2; t[(rg*4+3)*32+j]=a3;
    }
    __syncthreads();
    float* outp = (branch == 0) ? (g_xenc + g*2048) : (g_denc + g*2048);
    for (int idx = tid; idx < 16*32; idx += 512){
        int rg = idx >> 5, j = idx & 31;
        const float* ar = adj_s + rg*4*64;
        float bb = b3[j];
        float a0=bb,a1=bb,a2=bb,a3=bb;
        #pragma unroll 8
        for (int k = 0; k < 64; k++){
            float w = t[k*32+j];
            a0 += ar[k]*w; a1 += ar[64+k]*w; a2 += ar[128+k]*w; a3 += ar[192+k]*w;
        }
        h[(rg*4+0)*32+j]=a0; h[(rg*4+1)*32+j]=a1; h[(rg*4+2)*32+j]=a2; h[(rg*4+3)*32+j]=a3;
        outp[(rg*4+0)*32+j]=a0; outp[(rg*4+1)*32+j]=a1; outp[(rg*4+2)*32+j]=a2; outp[(rg*4+3)*32+j]=a3;
    }
    __syncthreads();
    if (branch == 0 && tid < 64){
        float s = 0.f;
        #pragma unroll
        for (int f = 0; f < 32; f++){ float v = h[tid*32+f]; s += v*v; }
        g_x2[g*64 + tid] = s;
    }
}

// ---------------- prep: vwd precompute + attn/bernoulli (512 threads) -----
__global__ void prep_kernel(const float* __restrict__ dp, const float* __restrict__ wl,
                            const float* __restrict__ fc1w, const float* __restrict__ fc2w,
                            const float* __restrict__ mlp_w, const float* __restrict__ mlp_b,
                            const float* __restrict__ mlp2_w, const float* __restrict__ mlp2_b)
{
    __shared__ float w3s[3*960];
    __shared__ float wls[960];
    __shared__ float yw[32][32];
    __shared__ float z[33];
    __shared__ float nrm[32];
    __shared__ float klsh[64];
    int tid = threadIdx.x;
    int d = blockIdx.x;

    for (int e = tid; e < 960; e += 512) wls[e] = wl[e];
    for (int e = tid; e < 2880; e += 512){
        int c = e / 960, j = e - c*960;
        float acc = 0.f;
        #pragma unroll 8
        for (int r = 0; r < 64; r++) acc += fc2w[c*64+r] * fc1w[r*960+j];
        w3s[e] = acc;
    }
    for (int e = tid; e < 1024; e += 512){
        int b = e >> 5, f = e & 31;
        float ss = 0.f, sw = 0.f;
        #pragma unroll 8
        for (int n = 0; n < 64; n++){
            float v = g_xenc[(b*64+n)*32 + f];
            ss += v*v;
            sw += mlp_w[n]*v;
        }
        yw[b][f] = sw / (sqrtf(ss) + 1e-12f);
    }
    const float* de = g_denc + d*2048;
    if (tid >= 64 && tid < 96){
        int f = tid - 64;
        float s = 0.f;
        #pragma unroll 8
        for (int m = 0; m < 64; m++){ float v = de[m*32+f]; s += v*v; }
        nrm[f] = sqrtf(s) + 1e-12f;
    }
    __syncthreads();
    {
        int base = d*32;
        for (int i = tid; i < 4096; i += 512){
            const float* dr = dp + (size_t)i*32;
            float s=0.f, t0=0.f, t1=0.f, t2=0.f;
            #pragma unroll 8
            for (int k = 0; k < 32; k++){
                float v = dr[k];
                s  += v * wls[base+k];
                t0 += v * w3s[base+k];
                t1 += v * w3s[960+base+k];
                t2 += v * w3s[1920+base+k];
            }
            g_vwd[d*4096 + i] = make_float4(s, t0, t1, t2);
        }
    }
    if (tid < 32){
        float acc = 0.f;
        #pragma unroll
        for (int b = 0; b < 32; b++) acc += mlp2_w[b]*yw[b][tid];
        z[tid] = acc;
    }
    if (tid == 32){
        float s = 0.f;
        #pragma unroll
        for (int b = 0; b < 32; b++) s += mlp2_w[b];
        z[32] = mlp_b[0]*s + mlp2_b[0];
    }
    __syncthreads();
    if (tid < 64){
        int m = tid;
        float p = z[32];
        #pragma unroll
        for (int f = 0; f < 32; f++) p += (de[m*32+f]/nrm[f]) * z[f];
        float attn = 1.f/(1.f + expf(-p));
        float u = jax_uniform_1920(d*64 + m);
        float bern = (u < attn) ? 1.f : 0.f;
        float ss = 0.f;
        #pragma unroll
        for (int f = 0; f < 32; f++){
            float v = de[m*32+f];
            g_dsamp[d*2048 + m*32+f] = bern*v;
            ss += v*v;
        }
        g_y2[d*64+m] = bern*ss;
        klsh[m] = attn*logf(attn*2.f) + (1.f-attn)*logf((1.f-attn)*2.f);
    }
    __syncthreads();
    if (tid == 0){
        float s = 0.f;
        for (int i = 0; i < 64; i++) s += klsh[i];
        g_klpart[d] = s;
    }
}

// ---------------- Sinkhorn: 2 groups x 256, f32x2-packed lambda pairs -----
// Group g handles pairs (g*4, g*4+1) and (g*4+2, g*4+3). Km packed float2
// per lambda-pair, stored TRANSPOSED in smem (Km2T[col*65+row]) so row reads
// are lane-consecutive. Column slice regA2[16] in registers. 2 passes/group.
__global__ void __launch_bounds__(512, 2)
sinkhorn_kernel(const int* __restrict__ num_node, const int* __restrict__ dict_nnode)
{
    extern __shared__ float S[];
    float* Ms   = S;                         // 64*68 floats = 17408 B
    u64*  Km2   = (u64*)(S + 4352);          // 2 groups * 4160 u64 = 66560 B
    u64*  ui2A  = Km2 + 2*4160;              // 2*64
    u64*  vi2A  = ui2A + 128;                // 2*64
    u64*  redA  = vi2A + 128;                // 2*4*64 = 512
    u64*  red2A = redA + 512;                // 512
    float* wjsA = (float*)(red2A + 512);     // 64
    float* wisA = wjsA + 64;                 // 64
    float4* wredA = (float4*)(wisA + 64);    // 2*8
    float4* wredB = wredA + 16;              // 2*8

    int d = blockIdx.x, b = blockIdx.y;
    int tid = threadIdx.x;
    int g  = tid >> 8;
    int gt = tid & 255;
    int c = gt & 63, q = gt >> 6;
    int lw = (tid >> 5) & 7;
    int nn = num_node[b], dn = dict_nnode[d];

    if (tid < 64){
        wisA[tid] = (tid < nn) ? 1.f/(float)nn : 0.f;
        wjsA[tid] = (tid < dn) ? 1.f/(float)dn : 0.f;
    }
    // stage xenc/dsamp into Km2 area (dead until first pass build)
    float* xs = (float*)Km2;
    float* ds = xs + 2048;
    {
        const float4* xg4 = (const float4*)(g_xenc + b*2048);
        const float4* dg4 = (const float4*)(g_dsamp + d*2048);
        float4* xs4 = (float4*)xs; float4* ds4 = (float4*)ds;
        for (int i = tid; i < 512; i += 512){ xs4[i] = xg4[i]; ds4[i] = dg4[i]; }
    }
    __syncthreads();
    for (int i = tid; i < 4096; i += 512){
        int n = i >> 6, m = i & 63;
        const float4* xr = (const float4*)(xs + n*32);
        const float4* dr = (const float4*)(ds + m*32);
        float acc = 0.f;
        #pragma unroll
        for (int j = 0; j < 8; j++){
            float4 a = xr[j], e = dr[j];
            acc += a.x*e.x + a.y*e.y + a.z*e.z + a.w*e.w;
        }
        Ms[n*68+m] = g_x2[b*64+n] + g_y2[d*64+m] - 2.f*acc;
    }
    __syncthreads();

    u64* Kg   = Km2 + g*4160;
    u64* uig  = ui2A + g*64;
    u64* vig  = vi2A + g*64;
    u64* redg = redA + g*256;
    u64* red2g = red2A + g*256;
    const float4* vw = g_vwd + d*4096;
    int base = q*16;

    for (int pass = 0; pass < 2; pass++){
        int la = g*4 + pass*2;
        float lama = c_lamda[la], lamb = c_lamda[la+1];

        // build packed transposed Km: (row,col) at Kg[col*65+row]
        for (int i = gt; i < 4096; i += 256){
            int row = i >> 6, col = i & 63;
            float mv = Ms[row*68 + col];
            u64 kv = 0ull;
            if (row < nn && col < dn)
                kv = pk2(__expf(-mv*lama), __expf(-mv*lamb));
            Kg[col*65 + row] = kv;
        }
        if (gt < 64) uig[gt] = pk2(1.f, 1.f);
        GBAR(g);

        // column slice into registers: rows base..base+15, col c
        u64 regA[16];
        #pragma unroll
        for (int n = 0; n < 16; n++) regA[n] = Kg[c*65 + base + n];

        for (int it = 0; it < 10; it++){
            // colsum partial (column c, rows base..base+15)
            u64 p = 0ull;
            const ulonglong2* u2 = (const ulonglong2*)(uig + base);
            #pragma unroll
            for (int k = 0; k < 8; k++){
                ulonglong2 uu = u2[k];
                FMA2(p, regA[2*k],   uu.x, p);
                FMA2(p, regA[2*k+1], uu.y, p);
            }
            redg[q*64 + c] = p;
            GBAR(g);
            if (gt < 64){
                u64 s01, s23, s;
                ADD2(s01, redg[gt], redg[64+gt]);
                ADD2(s23, redg[128+gt], redg[192+gt]);
                ADD2(s, s01, s23);
                float sx, sy; upk2(s, sx, sy);
                float wj = wjsA[gt];
                vig[gt] = pk2(__fdividef(wj, sx + 1e-6f), __fdividef(wj, sy + 1e-6f));
            }
            GBAR(g);
            // rowsum partial (row c, cols base..base+15), Km rows from smem
            p = 0ull;
            const ulonglong2* v2 = (const ulonglong2*)(vig + base);
            const u64* krow = Kg + c;
            #pragma unroll
            for (int k = 0; k < 8; k++){
                ulonglong2 vv = v2[k];
                FMA2(p, krow[(base + 2*k)*65],     vv.x, p);
                FMA2(p, krow[(base + 2*k + 1)*65], vv.y, p);
            }
            redg[q*64 + c] = p;
            GBAR(g);
            if (gt < 64){
                u64 s01, s23, s;
                ADD2(s01, redg[gt], redg[64+gt]);
                ADD2(s23, redg[128+gt], redg[192+gt]);
                ADD2(s, s01, s23);
                float sx, sy; upk2(s, sx, sy);
                float wi = wisA[gt];
                uig[gt] = pk2(__fdividef(wi, sx + 1e-6f), __fdividef(wi, sy + 1e-6f));
            }
            GBAR(g);
        }

        // ---- epilogue ----
        float uia, uib; upk2(uig[c], uia, uib);
        float gmxa=-3.4e38f, gmna=3.4e38f, gmxb=-3.4e38f, gmnb=3.4e38f;
        #pragma unroll
        for (int mm = 0; mm < 16; mm++){
            int col = base + mm;
            float va, vb; upk2(vig[col], va, vb);
            float ka, kb; upk2(Kg[col*65 + c], ka, kb);
            float ga = uia*ka*va, gb = uib*kb*vb;
            gmxa = fmaxf(gmxa, ga); gmna = fminf(gmna, ga);
            gmxb = fmaxf(gmxb, gb); gmnb = fminf(gmnb, gb);
        }
        redg[q*64+c]  = pk2(gmxa, gmxb);
        red2g[q*64+c] = pk2(gmna, gmnb);
        GBAR(g);
        float rmxa, rmxb, rmna, rmnb;
        {
            float x0,y0,x1,y1,x2,y2,x3,y3;
            upk2(redg[c], x0,y0);     upk2(redg[64+c], x1,y1);
            upk2(redg[128+c], x2,y2); upk2(redg[192+c], x3,y3);
            rmxa = fmaxf(fmaxf(x0,x1), fmaxf(x2,x3));
            rmxb = fmaxf(fmaxf(y0,y1), fmaxf(y2,y3));
            upk2(red2g[c], x0,y0);     upk2(red2g[64+c], x1,y1);
            upk2(red2g[128+c], x2,y2); upk2(red2g[192+c], x3,y3);
            rmna = fminf(fminf(x0,x1), fminf(x2,x3));
            rmnb = fminf(fminf(y0,y1), fminf(y2,y3));
        }
        float rinva = __fdividef(1.f, rmxa - rmna + 1e-6f);
        float rinvb = __fdividef(1.f, rmxb - rmnb + 1e-6f);

        float a0a=0.f,a1a=0.f,a2a=0.f,a3a=0.f;
        float a0b=0.f,a1b=0.f,a2b=0.f,a3b=0.f;
        #pragma unroll
        for (int mm = 0; mm < 16; mm++){
            int col = base + mm;
            float va, vb; upk2(vig[col], va, vb);
            float ka, kb; upk2(Kg[col*65 + c], ka, kb);
            float mval = Ms[c*68 + col];
            float4 w = vw[c*64 + col];
            float gma = (uia*ka*va - rmna)*rinva*mval;
            float gmb = (uib*kb*vb - rmnb)*rinvb*mval;
            a0a += gma*w.x; a1a += gma*w.y; a2a += gma*w.z; a3a += gma*w.w;
            a0b += gmb*w.x; a1b += gmb*w.y; a2b += gmb*w.z; a3b += gmb*w.w;
        }
        #pragma unroll
        for (int o = 16; o; o >>= 1){
            a0a += __shfl_xor_sync(0xffffffffu, a0a, o);
            a1a += __shfl_xor_sync(0xffffffffu, a1a, o);
            a2a += __shfl_xor_sync(0xffffffffu, a2a, o);
            a3a += __shfl_xor_sync(0xffffffffu, a3a, o);
            a0b += __shfl_xor_sync(0xffffffffu, a0b, o);
            a1b += __shfl_xor_sync(0xffffffffu, a1b, o);
            a2b += __shfl_xor_sync(0xffffffffu, a2b, o);
            a3b += __shfl_xor_sync(0xffffffffu, a3b, o);
        }
        if ((tid & 31) == 0){
            wredA[g*8 + lw] = make_float4(a0a,a1a,a2a,a3a);
            wredB[g*8 + lw] = make_float4(a0b,a1b,a2b,a3b);
        }
        GBAR(g);
        if (gt == 0){
            float4 s = wredA[g*8];
            #pragma unroll
            for (int w = 1; w < 8; w++){
                float4 t = wredA[g*8 + w];
                s.x += t.x; s.y += t.y; s.z += t.z; s.w += t.w;
            }
            g_part[(la*32+b)*30 + d] = s;
        } else if (gt == 32){
            float4 s = wredB[g*8];
            #pragma unroll
            for (int w = 1; w < 8; w++){
                float4 t = wredB[g*8 + w];
                s.x += t.x; s.y += t.y; s.z += t.z; s.w += t.w;
            }
            g_part[((la+1)*32+b)*30 + d] = s;
        }
        GBAR(g);   // protect Kg/uig/vig before next pass's rebuild
    }
}

// ---------------- final: softmax over l + folded head + KL ----------------
__global__ void final_kernel(const float* __restrict__ fc1b,
    const float* __restrict__ fc2w, const float* __restrict__ fc2b,
    float* __restrict__ out, int out_size)
{
    __shared__ float4 pl[8];
    int b = blockIdx.x, tid = threadIdx.x;
    int w = tid >> 5, lane = tid & 31;

    float4 a = make_float4(0.f,0.f,0.f,0.f);
    if (lane < 30) a = g_part[(w*32+b)*30 + lane];
    #pragma unroll
    for (int o = 16; o; o >>= 1){
        a.x += __shfl_xor_sync(0xffffffffu, a.x, o);
        a.y += __shfl_xor_sync(0xffffffffu, a.y, o);
        a.z += __shfl_xor_sync(0xffffffffu, a.z, o);
        a.w += __shfl_xor_sync(0xffffffffu, a.w, o);
    }
    if (lane == 0) pl[w] = a;
    __syncthreads();
    if (tid == 0){
        float mx = pl[0].x;
        #pragma unroll
        for (int l = 1; l < 8; l++) mx = fmaxf(mx, pl[l].x);
        float s = 0.f;
        float co[8];
        #pragma unroll
        for (int l = 0; l < 8; l++){ co[l] = expf(pl[l].x - mx); s += co[l]; }
        float t0=0.f, t1=0.f, t2=0.f;
        #pragma unroll
        for (int l = 0; l < 8; l++){
            float cf = co[l]/s;
            t0 += cf*pl[l].y; t1 += cf*pl[l].z; t2 += cf*pl[l].w;
        }
        float cc0=fc2b[0], cc1=fc2b[1], cc2=fc2b[2];
        for (int r = 0; r < 64; r++){
            float fb = fc1b[r];
            cc0 += fc2w[r]*fb; cc1 += fc2w[64+r]*fb; cc2 += fc2w[128+r]*fb;
        }
        out[b*3+0] = t0 + cc0;
        out[b*3+1] = t1 + cc1;
        out[b*3+2] = t2 + cc2;
    }
    if (b == 0 && tid == 32 && out_size > 96){
        float s = 0.f;
        for (int d = 0; d < 30; d++) s += g_klpart[d];
        out[96] = s;
    }
}

// ---------------- launch ---------------------------------------------------
extern "C" void kernel_launch(void* const* d_in, const int* in_sizes, int n_in,
                              void* d_out, int out_size)
{
    const float* x          = (const float*)d_in[0];
    const float* adj        = (const float*)d_in[1];
    const int*   num_node   = (const int*)  d_in[2];
    const float* dict_feat  = (const float*)d_in[3];
    const float* dict_adj   = (const float*)d_in[4];
    const int*   dict_nnode = (const int*)  d_in[5];
    const float* eW1 = (const float*)d_in[6];
    const float* eb1 = (const float*)d_in[7];
    const float* eW2 = (const float*)d_in[8];
    const float* eb2 = (const float*)d_in[9];
    const float* eW3 = (const float*)d_in[10];
    const float* eb3 = (const float*)d_in[11];
    const float* dW1 = (const float*)d_in[12];
    const float* db1 = (const float*)d_in[13];
    const float* dW2 = (const float*)d_in[14];
    const float* db2 = (const float*)d_in[15];
    const float* dW3 = (const float*)d_in[16];
    const float* db3 = (const float*)d_in[17];
    const float* mlp_w  = (const float*)d_in[18];
    const float* mlp_b  = (const float*)d_in[19];
    const float* mlp2_w = (const float*)d_in[20];
    const float* mlp2_b = (const float*)d_in[21];
    const float* dist_para    = (const float*)d_in[22];
    const float* weight_lamda = (const float*)d_in[23];
    const float* fc1_w = (const float*)d_in[24];
    const float* fc1_b = (const float*)d_in[25];
    const float* fc2_w = (const float*)d_in[26];
    const float* fc2_b = (const float*)d_in[27];

    const int gcn_smem = (4096 + 4096 + 8192 + 8192) * (int)sizeof(float);  // 96 KB
    // sinkhorn: Ms 17408 + Km2 66560 + ui/vi 2048 + red 4096 + red2 4096
    //           + wjs/wis 512 + wred 512 = 95232 B
    const int sink_smem = 95232;
    cudaFuncSetAttribute(gcn_kernel, cudaFuncAttributeMaxDynamicSharedMemorySize, gcn_smem);
    cudaFuncSetAttribute(sinkhorn_kernel, cudaFuncAttributeMaxDynamicSharedMemorySize, sink_smem);

    gcn_kernel<<<62, 512, gcn_smem>>>(x, adj, eW1, eb1, eW2, eb2, eW3, eb3,
                                      dict_feat, dict_adj, dW1, db1, dW2, db2, dW3, db3);
    prep_kernel<<<30, 512>>>(dist_para, weight_lamda, fc1_w, fc2_w,
                             mlp_w, mlp_b, mlp2_w, mlp2_b);
    sinkhorn_kernel<<<dim3(30, 32), 512, sink_smem>>>(num_node, dict_nnode);
    final_kernel<<<32, 256>>>(fc1_b, fc2_w, fc2_b, (float*)d_out, out_size);
}